// round 2
// baseline (speedup 1.0000x reference)
#include <cuda_runtime.h>

#define B2   8192
#define D    512
#define KDIM 1024
#define NM1  8191   // B2 - 1

// ---------------- scratch (device globals; no allocation allowed) ----------
__device__ float g_A[(size_t)B2 * KDIM];   // [x_i^2 | x_i]               32 MB
__device__ float g_B[(size_t)B2 * KDIM];   // [inv_s_j | -2 x_j inv_s_j]  32 MB
__device__ float g_t3[B2];
__device__ float g_ls[B2];
__device__ float g_c[B2];       // rowc_i = 0.1*gt_i + 0.5*ls_i
__device__ float g_pls[B2];     // ls[pos(j)]  (column-side term)
__device__ float g_rowsum[B2];

// ---------------- f32x2 helpers --------------------------------------------
__device__ __forceinline__ unsigned long long pack2(float lo, float hi) {
    unsigned long long r;
    asm("mov.b64 %0, {%1, %2};" : "=l"(r) : "f"(lo), "f"(hi));
    return r;
}
__device__ __forceinline__ void unpack2(unsigned long long v, float& lo, float& hi) {
    asm("mov.b64 {%0, %1}, %2;" : "=f"(lo), "=f"(hi) : "l"(v));
}
__device__ __forceinline__ void fma2(unsigned long long& d, unsigned long long a,
                                     unsigned long long b) {
    asm("fma.rn.f32x2 %0, %1, %2, %0;" : "+l"(d) : "l"(a), "l"(b));
}

// ---------------- prep: build A/B, t3, ls, zero rowsum ---------------------
__global__ void prep_kernel(const float* __restrict__ f, const float* __restrict__ s) {
    int i = blockIdx.x;
    int t = threadIdx.x;                    // 128 threads
    const float* fr = f + (size_t)i * D;
    const float* sr = s + (size_t)i * D;
    float* Ar = g_A + (size_t)i * KDIM;
    float* Br = g_B + (size_t)i * KDIM;
    float t3p = 0.f, lsp = 0.f;
    for (int d = t; d < D; d += 128) {
        float x   = fr[d];
        float sg  = sr[d];
        float inv = 1.0f / sg;
        Ar[d]       = x * x;
        Ar[D + d]   = x;
        Br[d]       = inv;
        Br[D + d]   = -2.0f * x * inv;
        t3p += x * x * inv;
        lsp += logf(sg);
    }
    __shared__ float sh1[128], sh2[128];
    sh1[t] = t3p; sh2[t] = lsp;
    __syncthreads();
    for (int st = 64; st > 0; st >>= 1) {
        if (t < st) { sh1[t] += sh1[t + st]; sh2[t] += sh2[t + st]; }
        __syncthreads();
    }
    if (t == 0) {
        g_t3[i]     = sh1[0];
        g_ls[i]     = sh2[0];
        g_rowsum[i] = 0.0f;
    }
}

// ---------------- per-row gt_i dot product + per-row / per-col constants ----
__global__ void gt_kernel(const int* __restrict__ label) {
    int i   = blockIdx.x;
    int lab = label[i];
    int pos = lab + (lab >= i ? 1 : 0);     // absolute index of i's positive
    const float* a = g_A + (size_t)i   * KDIM;
    const float* b = g_B + (size_t)pos * KDIM;
    float p = 0.f;
    for (int d = threadIdx.x; d < KDIM; d += 256) p += a[d] * b[d];
    __shared__ float sh[256];
    sh[threadIdx.x] = p;
    __syncthreads();
    for (int st = 128; st > 0; st >>= 1) {
        if (threadIdx.x < st) sh[threadIdx.x] += sh[threadIdx.x + st];
        __syncthreads();
    }
    if (threadIdx.x == 0) {
        float gt  = sh[0] + g_t3[pos];      // dist(i, pos(i))
        g_c[i]    = 0.1f * gt + 0.5f * g_ls[i];
        g_pls[i]  = g_ls[pos];              // column-side: ls of i's positive
    }
}

// ---------------- main fused dist-GEMM + epilogue ---------------------------
// 128x128 tile, BK=16, 256 threads (16x16), 8x8 per thread, f32x2 FMA.
__global__ __launch_bounds__(256, 2)
void dist_kernel(float* __restrict__ out, int write_logits) {
    __shared__ float As[16][136];   // transposed tiles; row stride 136 keeps
    __shared__ float Bs[16][136];   // float4 alignment (136*4 = 544 = 34*16)

    const int i0 = blockIdx.y * 128;
    const int j0 = blockIdx.x * 128;
    const int t  = threadIdx.x;
    const int tx = t & 15;
    const int ty = t >> 4;

    const float* Ag = g_A + (size_t)i0 * KDIM;
    const float* Bg = g_B + (size_t)j0 * KDIM;

    unsigned long long acc[8][4];
#pragma unroll
    for (int r = 0; r < 8; r++)
#pragma unroll
        for (int c = 0; c < 4; c++) acc[r][c] = 0ull;

    for (int k0 = 0; k0 < KDIM; k0 += 16) {
#pragma unroll
        for (int it = 0; it < 2; ++it) {
            int idx = t + it * 256;          // 512 float4 per matrix tile
            int row = idx >> 2;
            int kq  = (idx & 3) * 4;
            float4 va = *(const float4*)(Ag + (size_t)row * KDIM + k0 + kq);
            float4 vb = *(const float4*)(Bg + (size_t)row * KDIM + k0 + kq);
            As[kq + 0][row] = va.x; As[kq + 1][row] = va.y;
            As[kq + 2][row] = va.z; As[kq + 3][row] = va.w;
            Bs[kq + 0][row] = vb.x; Bs[kq + 1][row] = vb.y;
            Bs[kq + 2][row] = vb.z; Bs[kq + 3][row] = vb.w;
        }
        __syncthreads();

#pragma unroll
        for (int kk = 0; kk < 16; kk++) {
            float4 a0 = *(const float4*)&As[kk][ty * 8];
            float4 a1 = *(const float4*)&As[kk][ty * 8 + 4];
            float4 b0 = *(const float4*)&Bs[kk][tx * 8];
            float4 b1 = *(const float4*)&Bs[kk][tx * 8 + 4];

            union { float4 f; unsigned long long u[2]; } ub0, ub1;
            ub0.f = b0; ub1.f = b1;
            unsigned long long bp[4] = { ub0.u[0], ub0.u[1], ub1.u[0], ub1.u[1] };

            float av[8] = { a0.x, a0.y, a0.z, a0.w, a1.x, a1.y, a1.z, a1.w };
#pragma unroll
            for (int r = 0; r < 8; r++) {
                unsigned long long ap = pack2(av[r], av[r]);
#pragma unroll
                for (int c = 0; c < 4; c++) fma2(acc[r][c], ap, bp[c]);
            }
        }
        __syncthreads();
    }

    // ---- epilogue: dist -> exp -> skip-self scatter + row sums ----
    float t3v[8], colv[8], cv[8];
#pragma unroll
    for (int c = 0; c < 8; c++) {
        int jg  = j0 + tx * 8 + c;
        t3v[c]  = g_t3[jg];
        colv[c] = -0.5f * g_pls[jg];        // -0.5 * ls[pos(j)]
    }
#pragma unroll
    for (int r = 0; r < 8; r++) cv[r] = g_c[i0 + ty * 8 + r];

#pragma unroll
    for (int r = 0; r < 8; r++) {
        const int ig = i0 + ty * 8 + r;
        float rs = 0.f;
#pragma unroll
        for (int c2 = 0; c2 < 4; c2++) {
            float lo, hi;
            unpack2(acc[r][c2], lo, hi);
#pragma unroll
            for (int h = 0; h < 2; h++) {
                int   c    = c2 * 2 + h;
                int   jg   = j0 + tx * 8 + c;
                float dist = (h == 0 ? lo : hi) + t3v[c];
                float lg   = __expf(cv[r] + colv[c] - 0.1f * dist);
                if (jg != ig) {
                    rs += lg;
                    if (write_logits) {
                        int kcol = jg - (jg > ig ? 1 : 0);
                        out[(size_t)ig * NM1 + kcol] = lg;
                    }
                }
            }
        }
        // reduce rs across the 16 lanes (same ty) of this half-warp
#pragma unroll
        for (int off = 8; off > 0; off >>= 1)
            rs += __shfl_down_sync(0xFFFFFFFFu, rs, off);
        if (tx == 0) atomicAdd(&g_rowsum[ig], rs);
    }
}

// ---------------- loss = mean(log(rowsum)) ----------------------------------
__global__ void loss_kernel(float* __restrict__ loss_out) {
    __shared__ float sh[1024];
    float p = 0.f;
    for (int i = threadIdx.x; i < B2; i += 1024) p += logf(g_rowsum[i]);
    sh[threadIdx.x] = p;
    __syncthreads();
    for (int st = 512; st > 0; st >>= 1) {
        if (threadIdx.x < st) sh[threadIdx.x] += sh[threadIdx.x + st];
        __syncthreads();
    }
    if (threadIdx.x == 0) *loss_out = sh[0] / (float)B2;
}

// ---------------- launch -----------------------------------------------------
extern "C" void kernel_launch(void* const* d_in, const int* in_sizes, int n_in,
                              void* d_out, int out_size) {
    const float* f     = (const float*)d_in[0];
    const float* s     = (const float*)d_in[1];
    const int*   label = (const int*)d_in[2];

    float* outf = (float*)d_out;
    const long long LOGN = (long long)B2 * NM1;

    float* loss_out  = nullptr;
    float* logit_out = nullptr;
    if ((long long)out_size == LOGN + 1) { loss_out = outf; logit_out = outf + 1; }
    else if ((long long)out_size == LOGN) { logit_out = outf; }
    else { loss_out = outf; }   // scalar-only fallback

    prep_kernel<<<B2, 128>>>(f, s);
    gt_kernel<<<B2, 256>>>(label);

    dim3 grid(B2 / 128, B2 / 128);
    dist_kernel<<<grid, 256>>>(logit_out ? logit_out : outf,
                               logit_out != nullptr ? 1 : 0);

    if (loss_out) loss_kernel<<<1, 1024>>>(loss_out);
}

// round 4
// speedup vs baseline: 1.8973x; 1.8973x over previous
#include <cuda_runtime.h>
#include <cuda_bf16.h>
#include <cstdint>

#define B2   8192
#define D    512
#define KD   2048      // bf16 cols: [0,1024) hi, [1024,2048) lo
#define NM1  8191

#define TM   256
#define TN   128
#define BK   32        // bf16 per chunk (64 B rows)
#define NSTG 4
#define NCH  96        // 3 products * 32 chunks

// smem: padded rows of 40 bf16 (80 B) -> ldmatrix conflict-free
#define LDS_ROW 80
#define A_SZ (256 * LDS_ROW)          // 20480
#define B_SZ (128 * LDS_ROW)          // 10240
#define STAGE_SZ (A_SZ + B_SZ)        // 30720
#define SM_TOTAL (NSTG * STAGE_SZ)    // 122880

// ---------------- device scratch ----------------
__device__ __align__(128) __nv_bfloat16 g_Abf[(size_t)B2 * KD];  // [x^2 hi|x hi|x^2 lo|x lo]
__device__ __align__(128) __nv_bfloat16 g_Bbf[(size_t)B2 * KD];  // [1/s hi|-2x/s hi|lo|lo]
__device__ float g_t3[B2];
__device__ float g_ls[B2];
__device__ float g_c[B2];      // 0.1*gt_i + 0.5*ls_i
__device__ float g_cj[B2];     // -0.5*ls[pos(j)] - 0.1*t3[j]
__device__ float g_rowsum[B2];

// ---------------- PTX helpers ----------------
__device__ __forceinline__ uint32_t smem_u32(const void* p) {
    uint32_t a;
    asm("{ .reg .u64 t; cvta.to.shared.u64 t, %1; cvt.u32.u64 %0, t; }" : "=r"(a) : "l"(p));
    return a;
}
__device__ __forceinline__ void cp_async16(uint32_t dst, const void* src) {
    asm volatile("cp.async.cg.shared.global [%0], [%1], 16;" :: "r"(dst), "l"(src) : "memory");
}
__device__ __forceinline__ void cp_commit() {
    asm volatile("cp.async.commit_group;" ::: "memory");
}
template <int N> __device__ __forceinline__ void cp_wait() {
    asm volatile("cp.async.wait_group %0;" :: "n"(N) : "memory");
}
__device__ __forceinline__ void ldsm4(uint32_t addr, uint32_t* r) {
    asm volatile("ldmatrix.sync.aligned.m8n8.x4.shared.b16 {%0,%1,%2,%3}, [%4];"
                 : "=r"(r[0]), "=r"(r[1]), "=r"(r[2]), "=r"(r[3]) : "r"(addr));
}
__device__ __forceinline__ void mma16816(float* d, const uint32_t* a,
                                         uint32_t b0, uint32_t b1) {
    asm volatile(
        "mma.sync.aligned.m16n8k16.row.col.f32.bf16.bf16.f32 "
        "{%0,%1,%2,%3}, {%4,%5,%6,%7}, {%8,%9}, {%0,%1,%2,%3};"
        : "+f"(d[0]), "+f"(d[1]), "+f"(d[2]), "+f"(d[3])
        : "r"(a[0]), "r"(a[1]), "r"(a[2]), "r"(a[3]), "r"(b0), "r"(b1));
}

// ---------------- prep: bf16 splits + t3 + ls ----------------
__global__ void prep_kernel(const float* __restrict__ f, const float* __restrict__ s) {
    int i = blockIdx.x;
    int t = threadIdx.x;  // 128
    const float* fr = f + (size_t)i * D;
    const float* sr = s + (size_t)i * D;
    __nv_bfloat16* Ar = g_Abf + (size_t)i * KD;
    __nv_bfloat16* Br = g_Bbf + (size_t)i * KD;
    float t3p = 0.f, lsp = 0.f;
    for (int d = t; d < D; d += 128) {
        float x = fr[d], sg = sr[d];
        float inv = 1.0f / sg;
        float a1 = x * x, a2 = x, b1 = inv, b2 = -2.0f * x * inv;
        __nv_bfloat16 h;
        h = __float2bfloat16(a1); Ar[d]       = h; Ar[1024 + d] = __float2bfloat16(a1 - __bfloat162float(h));
        h = __float2bfloat16(a2); Ar[512 + d] = h; Ar[1536 + d] = __float2bfloat16(a2 - __bfloat162float(h));
        h = __float2bfloat16(b1); Br[d]       = h; Br[1024 + d] = __float2bfloat16(b1 - __bfloat162float(h));
        h = __float2bfloat16(b2); Br[512 + d] = h; Br[1536 + d] = __float2bfloat16(b2 - __bfloat162float(h));
        t3p += a1 * inv;
        lsp += logf(sg);
    }
    __shared__ float sh1[128], sh2[128];
    sh1[t] = t3p; sh2[t] = lsp;
    __syncthreads();
    for (int st = 64; st > 0; st >>= 1) {
        if (t < st) { sh1[t] += sh1[t + st]; sh2[t] += sh2[t + st]; }
        __syncthreads();
    }
    if (t == 0) { g_t3[i] = sh1[0]; g_ls[i] = sh2[0]; g_rowsum[i] = 0.f; }
}

// ---------------- gt + per-row/col constants ----------------
__global__ void gt_kernel(const float* __restrict__ f, const float* __restrict__ s,
                          const int* __restrict__ label) {
    int i = blockIdx.x;
    int lab = label[i];
    int pos = lab + (lab >= i ? 1 : 0);
    const float* xi = f + (size_t)i * D;
    const float* xp = f + (size_t)pos * D;
    const float* sp = s + (size_t)pos * D;
    float p = 0.f;
    for (int d = threadIdx.x; d < D; d += 256) {
        float dd = xi[d] - xp[d];
        p += dd * dd / sp[d];
    }
    __shared__ float sh[256];
    sh[threadIdx.x] = p;
    __syncthreads();
    for (int st = 128; st > 0; st >>= 1) {
        if (threadIdx.x < st) sh[threadIdx.x] += sh[threadIdx.x + st];
        __syncthreads();
    }
    if (threadIdx.x == 0) {
        g_c[i]  = 0.1f * sh[0] + 0.5f * g_ls[i];
        g_cj[i] = -0.5f * g_ls[pos] - 0.1f * g_t3[i];
    }
}

// ---------------- chunk loader ----------------
__device__ __forceinline__ void load_chunk(int c, int st, int i0, int j0, uint32_t sb) {
    const int p  = c >> 5;
    const int kk = (c & 31) * BK;
    const int acol = (p == 2 ? 1024 : 0) + kk;
    const int bcol = (p == 1 ? 1024 : 0) + kk;
    const uint32_t aS = sb + st * STAGE_SZ;
    const uint32_t bS = aS + A_SZ;
    const int tid = threadIdx.x;
#pragma unroll
    for (int it = 0; it < 4; it++) {            // A: 1024 16B chunks
        int id = tid + it * 256;
        int row = id >> 2, kc = id & 3;
        cp_async16(aS + row * LDS_ROW + kc * 16,
                   g_Abf + (size_t)(i0 + row) * KD + acol + kc * 8);
    }
#pragma unroll
    for (int it = 0; it < 2; it++) {            // B: 512 16B chunks
        int id = tid + it * 256;
        int row = id >> 2, kc = id & 3;
        cp_async16(bS + row * LDS_ROW + kc * 16,
                   g_Bbf + (size_t)(j0 + row) * KD + bcol + kc * 8);
    }
}

// ---------------- main HMMA dist kernel ----------------
__global__ __launch_bounds__(256)
void dist_kernel(float* __restrict__ out, int write_logits) {
    extern __shared__ char smem[];
    const uint32_t sb = smem_u32(smem);
    const int tid  = threadIdx.x;
    const int lane = tid & 31;
    const int wid  = tid >> 5;
    const int wm   = wid & 3;        // 4 M groups of 64
    const int wn   = wid >> 2;       // 2 N groups of 64
    const int i0 = blockIdx.y * TM;
    const int j0 = blockIdx.x * TN;

    float acc[4][8][4];
#pragma unroll
    for (int mi = 0; mi < 4; mi++)
#pragma unroll
        for (int ni = 0; ni < 8; ni++)
#pragma unroll
            for (int q = 0; q < 4; q++) acc[mi][ni][q] = 0.f;

    // prologue
#pragma unroll
    for (int s = 0; s < NSTG - 1; s++) { load_chunk(s, s, i0, j0, sb); cp_commit(); }

    const uint32_t aoff = (wm * 64 + (lane & 15)) * LDS_ROW + (lane >> 4) * 16;
    const uint32_t boff = (wn * 64 + (lane & 15)) * LDS_ROW + (lane >> 4) * 16;

    for (int c = 0; c < NCH; c++) {
        int pf = c + NSTG - 1;
        if (pf < NCH) load_chunk(pf, pf % NSTG, i0, j0, sb);
        cp_commit();
        cp_wait<NSTG - 1>();
        __syncthreads();

        const uint32_t aS = sb + (c % NSTG) * STAGE_SZ;
        const uint32_t bS = aS + A_SZ;
#pragma unroll
        for (int ks = 0; ks < 2; ks++) {
            uint32_t a[4][4], b[4][4];
#pragma unroll
            for (int mi = 0; mi < 4; mi++)
                ldsm4(aS + aoff + mi * (16 * LDS_ROW) + ks * 32, a[mi]);
#pragma unroll
            for (int np = 0; np < 4; np++)
                ldsm4(bS + boff + np * (16 * LDS_ROW) + ks * 32, b[np]);
#pragma unroll
            for (int mi = 0; mi < 4; mi++)
#pragma unroll
                for (int ni = 0; ni < 8; ni++)
                    mma16816(acc[mi][ni], a[mi],
                             b[ni >> 1][ni & 1], b[ni >> 1][(ni & 1) + 2]);
        }
        __syncthreads();
    }

    // ---------------- epilogue ----------------
    float cv0[4], cv1[4];
#pragma unroll
    for (int mi = 0; mi < 4; mi++) {
        int r0 = i0 + wm * 64 + mi * 16 + (lane >> 2);
        cv0[mi] = g_c[r0];
        cv1[mi] = g_c[r0 + 8];
    }
    float cjv[8][2];
#pragma unroll
    for (int ni = 0; ni < 8; ni++) {
        int cb = j0 + wn * 64 + (ni >> 1) * 16 + (ni & 1) * 8 + (lane & 3) * 2;
        cjv[ni][0] = g_cj[cb];
        cjv[ni][1] = g_cj[cb + 1];
    }

#pragma unroll
    for (int mi = 0; mi < 4; mi++) {
        const int r0 = i0 + wm * 64 + mi * 16 + (lane >> 2);
        const int r1 = r0 + 8;
        float rs0 = 0.f, rs1 = 0.f;
#pragma unroll
        for (int ni = 0; ni < 8; ni++) {
            const int cb = j0 + wn * 64 + (ni >> 1) * 16 + (ni & 1) * 8 + (lane & 3) * 2;
            float e0 = __expf(cv0[mi] + cjv[ni][0] - 0.1f * acc[mi][ni][0]);
            float e1 = __expf(cv0[mi] + cjv[ni][1] - 0.1f * acc[mi][ni][1]);
            float e2 = __expf(cv1[mi] + cjv[ni][0] - 0.1f * acc[mi][ni][2]);
            float e3 = __expf(cv1[mi] + cjv[ni][1] - 0.1f * acc[mi][ni][3]);
            if (cb     == r0) e0 = 0.f;
            if (cb + 1 == r0) e1 = 0.f;
            if (cb     == r1) e2 = 0.f;
            if (cb + 1 == r1) e3 = 0.f;
            rs0 += e0 + e1;
            rs1 += e2 + e3;
            if (write_logits) {
                if (cb     != r0) out[(size_t)r0 * NM1 + cb     - (cb     > r0)] = e0;
                if (cb + 1 != r0) out[(size_t)r0 * NM1 + cb + 1 - (cb + 1 > r0)] = e1;
                if (cb     != r1) out[(size_t)r1 * NM1 + cb     - (cb     > r1)] = e2;
                if (cb + 1 != r1) out[(size_t)r1 * NM1 + cb + 1 - (cb + 1 > r1)] = e3;
            }
        }
        rs0 += __shfl_xor_sync(0xFFFFFFFFu, rs0, 1);
        rs0 += __shfl_xor_sync(0xFFFFFFFFu, rs0, 2);
        rs1 += __shfl_xor_sync(0xFFFFFFFFu, rs1, 1);
        rs1 += __shfl_xor_sync(0xFFFFFFFFu, rs1, 2);
        if ((lane & 3) == 0) {
            atomicAdd(&g_rowsum[r0], rs0);
            atomicAdd(&g_rowsum[r1], rs1);
        }
    }
}

// ---------------- loss = mean(log(rowsum)) ----------------
__global__ void loss_kernel(float* __restrict__ loss_out) {
    __shared__ float sh[1024];
    float p = 0.f;
    for (int i = threadIdx.x; i < B2; i += 1024) p += logf(g_rowsum[i]);
    sh[threadIdx.x] = p;
    __syncthreads();
    for (int st = 512; st > 0; st >>= 1) {
        if (threadIdx.x < st) sh[threadIdx.x] += sh[threadIdx.x + st];
        __syncthreads();
    }
    if (threadIdx.x == 0) *loss_out = sh[0] / (float)B2;
}

// ---------------- launch ----------------
extern "C" void kernel_launch(void* const* d_in, const int* in_sizes, int n_in,
                              void* d_out, int out_size) {
    const float* f     = (const float*)d_in[0];
    const float* s     = (const float*)d_in[1];
    const int*   label = (const int*)d_in[2];

    float* outf = (float*)d_out;
    const long long LOGN = (long long)B2 * NM1;
    float* loss_out  = nullptr;
    float* logit_out = nullptr;
    if ((long long)out_size == LOGN + 1) { loss_out = outf; logit_out = outf + 1; }
    else if ((long long)out_size == LOGN) { logit_out = outf; }
    else { loss_out = outf; }

    cudaFuncSetAttribute(dist_kernel, cudaFuncAttributeMaxDynamicSharedMemorySize, SM_TOTAL);

    prep_kernel<<<B2, 128>>>(f, s);
    gt_kernel<<<B2, 256>>>(f, s, label);

    dim3 grid(B2 / TN, B2 / TM);
    dist_kernel<<<grid, 256, SM_TOTAL>>>(logit_out ? logit_out : outf,
                                         logit_out != nullptr ? 1 : 0);

    if (loss_out) loss_kernel<<<1, 1024>>>(loss_out);
}

// round 5
// speedup vs baseline: 2.2426x; 1.1820x over previous
#include <cuda_runtime.h>
#include <cuda_bf16.h>
#include <cstdint>

#define B2   8192
#define D    512
#define KD   2048      // bf16 cols: [0,1024) hi, [1024,2048) lo
#define NM1  8191

#define TM   256
#define TN   128
#define BK   64        // bf16 per chunk (128 B rows)
#define NSTG 3
#define NCH  48        // 3 products * 16 chunks

#define ROWB 144                       // 128 B data + 16 B pad
#define A_SZ (256 * ROWB)              // 36864
#define B_SZ (128 * ROWB)              // 18432
#define STAGE_SZ (A_SZ + B_SZ)         // 55296
#define SM_TOTAL (NSTG * STAGE_SZ)     // 165888

// ---------------- device scratch ----------------
__device__ __align__(128) __nv_bfloat16 g_Abf[(size_t)B2 * KD];
__device__ __align__(128) __nv_bfloat16 g_Bbf[(size_t)B2 * KD];
__device__ float g_t3[B2];
__device__ float g_ls[B2];
__device__ float g_c[B2];      // 0.1*gt_i + 0.5*ls_i
__device__ float g_cj[B2];     // -0.5*ls[pos(j)] - 0.1*t3[j]
__device__ float g_rowsum[B2];

// ---------------- PTX helpers ----------------
__device__ __forceinline__ uint32_t smem_u32(const void* p) {
    uint32_t a;
    asm("{ .reg .u64 t; cvta.to.shared.u64 t, %1; cvt.u32.u64 %0, t; }" : "=r"(a) : "l"(p));
    return a;
}
__device__ __forceinline__ void cp_async16(uint32_t dst, const void* src) {
    asm volatile("cp.async.cg.shared.global [%0], [%1], 16;" :: "r"(dst), "l"(src) : "memory");
}
__device__ __forceinline__ void cp_commit() {
    asm volatile("cp.async.commit_group;" ::: "memory");
}
template <int N> __device__ __forceinline__ void cp_wait() {
    asm volatile("cp.async.wait_group %0;" :: "n"(N) : "memory");
}
__device__ __forceinline__ void ldsm4(uint32_t addr, uint32_t* r) {
    asm volatile("ldmatrix.sync.aligned.m8n8.x4.shared.b16 {%0,%1,%2,%3}, [%4];"
                 : "=r"(r[0]), "=r"(r[1]), "=r"(r[2]), "=r"(r[3]) : "r"(addr));
}
__device__ __forceinline__ void mma16816(float* d, const uint32_t* a,
                                         uint32_t b0, uint32_t b1) {
    asm volatile(
        "mma.sync.aligned.m16n8k16.row.col.f32.bf16.bf16.f32 "
        "{%0,%1,%2,%3}, {%4,%5,%6,%7}, {%8,%9}, {%0,%1,%2,%3};"
        : "+f"(d[0]), "+f"(d[1]), "+f"(d[2]), "+f"(d[3])
        : "r"(a[0]), "r"(a[1]), "r"(a[2]), "r"(a[3]), "r"(b0), "r"(b1));
}

// ---------------- prep: bf16 splits + t3 + ls ----------------
__global__ void prep_kernel(const float* __restrict__ f, const float* __restrict__ s) {
    int i = blockIdx.x;
    int t = threadIdx.x;  // 128
    const float* fr = f + (size_t)i * D;
    const float* sr = s + (size_t)i * D;
    __nv_bfloat16* Ar = g_Abf + (size_t)i * KD;
    __nv_bfloat16* Br = g_Bbf + (size_t)i * KD;
    float t3p = 0.f, lsp = 0.f;
    for (int d = t; d < D; d += 128) {
        float x = fr[d], sg = sr[d];
        float inv = 1.0f / sg;
        float a1 = x * x, a2 = x, b1 = inv, b2 = -2.0f * x * inv;
        __nv_bfloat16 h;
        h = __float2bfloat16(a1); Ar[d]       = h; Ar[1024 + d] = __float2bfloat16(a1 - __bfloat162float(h));
        h = __float2bfloat16(a2); Ar[512 + d] = h; Ar[1536 + d] = __float2bfloat16(a2 - __bfloat162float(h));
        h = __float2bfloat16(b1); Br[d]       = h; Br[1024 + d] = __float2bfloat16(b1 - __bfloat162float(h));
        h = __float2bfloat16(b2); Br[512 + d] = h; Br[1536 + d] = __float2bfloat16(b2 - __bfloat162float(h));
        t3p += a1 * inv;
        lsp += logf(sg);
    }
    __shared__ float sh1[128], sh2[128];
    sh1[t] = t3p; sh2[t] = lsp;
    __syncthreads();
    for (int st = 64; st > 0; st >>= 1) {
        if (t < st) { sh1[t] += sh1[t + st]; sh2[t] += sh2[t + st]; }
        __syncthreads();
    }
    if (t == 0) { g_t3[i] = sh1[0]; g_ls[i] = sh2[0]; g_rowsum[i] = 0.f; }
}

// ---------------- gt + per-row/col constants ----------------
__global__ void gt_kernel(const float* __restrict__ f, const float* __restrict__ s,
                          const int* __restrict__ label) {
    int i = blockIdx.x;
    int lab = label[i];
    int pos = lab + (lab >= i ? 1 : 0);
    const float* xi = f + (size_t)i * D;
    const float* xp = f + (size_t)pos * D;
    const float* sp = s + (size_t)pos * D;
    float p = 0.f;
    for (int d = threadIdx.x; d < D; d += 256) {
        float dd = xi[d] - xp[d];
        p += dd * dd / sp[d];
    }
    __shared__ float sh[256];
    sh[threadIdx.x] = p;
    __syncthreads();
    for (int st = 128; st > 0; st >>= 1) {
        if (threadIdx.x < st) sh[threadIdx.x] += sh[threadIdx.x + st];
        __syncthreads();
    }
    if (threadIdx.x == 0) {
        g_c[i]  = 0.1f * sh[0] + 0.5f * g_ls[i];
        g_cj[i] = -0.5f * g_ls[pos] - 0.1f * g_t3[i];
    }
}

// ---------------- chunk loader (BK=64) ----------------
__device__ __forceinline__ void load_chunk(int c, int st, int i0, int j0, uint32_t sb) {
    const int p  = c >> 4;
    const int kk = (c & 15) * BK;
    const int acol = (p == 2 ? 1024 : 0) + kk;
    const int bcol = (p == 1 ? 1024 : 0) + kk;
    const uint32_t aS = sb + st * STAGE_SZ;
    const uint32_t bS = aS + A_SZ;
    const int tid = threadIdx.x;
#pragma unroll
    for (int it = 0; it < 8; it++) {            // A: 2048 16B segs
        int id = tid + it * 256;
        int row = id >> 3, kc = id & 7;
        cp_async16(aS + row * ROWB + kc * 16,
                   g_Abf + (size_t)(i0 + row) * KD + acol + kc * 8);
    }
#pragma unroll
    for (int it = 0; it < 4; it++) {            // B: 1024 16B segs
        int id = tid + it * 256;
        int row = id >> 3, kc = id & 7;
        cp_async16(bS + row * ROWB + kc * 16,
                   g_Bbf + (size_t)(j0 + row) * KD + bcol + kc * 8);
    }
}

// ---------------- main HMMA dist kernel ----------------
__global__ __launch_bounds__(256)
void dist_kernel(float* __restrict__ out, int write_logits) {
    extern __shared__ char smem[];
    const uint32_t sb = smem_u32(smem);
    const int tid  = threadIdx.x;
    const int lane = tid & 31;
    const int wid  = tid >> 5;
    const int wm   = wid & 3;        // 4 M groups of 64
    const int wn   = wid >> 2;       // 2 N groups of 64
    const int i0 = blockIdx.y * TM;
    const int j0 = blockIdx.x * TN;

    float acc[4][8][4];
#pragma unroll
    for (int mi = 0; mi < 4; mi++)
#pragma unroll
        for (int ni = 0; ni < 8; ni++)
#pragma unroll
            for (int q = 0; q < 4; q++) acc[mi][ni][q] = 0.f;

    // prologue: stages 0,1
#pragma unroll
    for (int s = 0; s < NSTG - 1; s++) { load_chunk(s, s, i0, j0, sb); cp_commit(); }

    const uint32_t aoff = (wm * 64 + (lane & 15)) * ROWB + (lane >> 4) * 16;
    const uint32_t boff = (wn * 64 + (lane & 15)) * ROWB + (lane >> 4) * 16;

    uint32_t afr[2][4][4], bfr[2][4][4];

    for (int c = 0; c < NCH; c++) {
        cp_wait<NSTG - 2>();
        __syncthreads();
        // prefetch chunk c+2 into stage (c+2)%3 == (c-1)%3 (free after sync)
        int pf = c + NSTG - 1;
        if (pf < NCH) load_chunk(pf, pf % NSTG, i0, j0, sb);
        cp_commit();

        const uint32_t aS = sb + (c % NSTG) * STAGE_SZ;
        const uint32_t bS = aS + A_SZ;

        // load ks=0 fragments
#pragma unroll
        for (int mi = 0; mi < 4; mi++) ldsm4(aS + aoff + mi * (16 * ROWB), afr[0][mi]);
#pragma unroll
        for (int np = 0; np < 4; np++) ldsm4(bS + boff + np * (16 * ROWB), bfr[0][np]);

#pragma unroll
        for (int ks = 0; ks < 4; ks++) {
            const int cur = ks & 1, nxt = cur ^ 1;
            if (ks < 3) {
#pragma unroll
                for (int mi = 0; mi < 4; mi++)
                    ldsm4(aS + aoff + mi * (16 * ROWB) + (ks + 1) * 32, afr[nxt][mi]);
#pragma unroll
                for (int np = 0; np < 4; np++)
                    ldsm4(bS + boff + np * (16 * ROWB) + (ks + 1) * 32, bfr[nxt][np]);
            }
#pragma unroll
            for (int mi = 0; mi < 4; mi++)
#pragma unroll
                for (int ni = 0; ni < 8; ni++)
                    mma16816(acc[mi][ni], afr[cur][mi],
                             bfr[cur][ni >> 1][ni & 1], bfr[cur][ni >> 1][(ni & 1) + 2]);
        }
    }

    // ---------------- epilogue ----------------
    float cv0[4], cv1[4];
#pragma unroll
    for (int mi = 0; mi < 4; mi++) {
        int r0 = i0 + wm * 64 + mi * 16 + (lane >> 2);
        cv0[mi] = g_c[r0];
        cv1[mi] = g_c[r0 + 8];
    }
    float cjv[8][2];
#pragma unroll
    for (int ni = 0; ni < 8; ni++) {
        int cb = j0 + wn * 64 + (ni >> 1) * 16 + (ni & 1) * 8 + (lane & 3) * 2;
        cjv[ni][0] = g_cj[cb];
        cjv[ni][1] = g_cj[cb + 1];
    }

#pragma unroll
    for (int mi = 0; mi < 4; mi++) {
        const int r0 = i0 + wm * 64 + mi * 16 + (lane >> 2);
        const int r1 = r0 + 8;
        float rs0 = 0.f, rs1 = 0.f;
#pragma unroll
        for (int ni = 0; ni < 8; ni++) {
            const int cb = j0 + wn * 64 + (ni >> 1) * 16 + (ni & 1) * 8 + (lane & 3) * 2;
            float e0 = __expf(cv0[mi] + cjv[ni][0] - 0.1f * acc[mi][ni][0]);
            float e1 = __expf(cv0[mi] + cjv[ni][1] - 0.1f * acc[mi][ni][1]);
            float e2 = __expf(cv1[mi] + cjv[ni][0] - 0.1f * acc[mi][ni][2]);
            float e3 = __expf(cv1[mi] + cjv[ni][1] - 0.1f * acc[mi][ni][3]);
            if (cb     == r0) e0 = 0.f;
            if (cb + 1 == r0) e1 = 0.f;
            if (cb     == r1) e2 = 0.f;
            if (cb + 1 == r1) e3 = 0.f;
            rs0 += e0 + e1;
            rs1 += e2 + e3;
            if (write_logits) {
                if (cb     != r0) out[(size_t)r0 * NM1 + cb     - (cb     > r0)] = e0;
                if (cb + 1 != r0) out[(size_t)r0 * NM1 + cb + 1 - (cb + 1 > r0)] = e1;
                if (cb     != r1) out[(size_t)r1 * NM1 + cb     - (cb     > r1)] = e2;
                if (cb + 1 != r1) out[(size_t)r1 * NM1 + cb + 1 - (cb + 1 > r1)] = e3;
            }
        }
        rs0 += __shfl_xor_sync(0xFFFFFFFFu, rs0, 1);
        rs0 += __shfl_xor_sync(0xFFFFFFFFu, rs0, 2);
        rs1 += __shfl_xor_sync(0xFFFFFFFFu, rs1, 1);
        rs1 += __shfl_xor_sync(0xFFFFFFFFu, rs1, 2);
        if ((lane & 3) == 0) {
            atomicAdd(&g_rowsum[r0], rs0);
            atomicAdd(&g_rowsum[r1], rs1);
        }
    }
}

// ---------------- loss = mean(log(rowsum)) ----------------
__global__ void loss_kernel(float* __restrict__ loss_out) {
    __shared__ float sh[1024];
    float p = 0.f;
    for (int i = threadIdx.x; i < B2; i += 1024) p += logf(g_rowsum[i]);
    sh[threadIdx.x] = p;
    __syncthreads();
    for (int st = 512; st > 0; st >>= 1) {
        if (threadIdx.x < st) sh[threadIdx.x] += sh[threadIdx.x + st];
        __syncthreads();
    }
    if (threadIdx.x == 0) *loss_out = sh[0] / (float)B2;
}

// ---------------- launch ----------------
extern "C" void kernel_launch(void* const* d_in, const int* in_sizes, int n_in,
                              void* d_out, int out_size) {
    const float* f     = (const float*)d_in[0];
    const float* s     = (const float*)d_in[1];
    const int*   label = (const int*)d_in[2];

    float* outf = (float*)d_out;
    const long long LOGN = (long long)B2 * NM1;
    float* loss_out  = nullptr;
    float* logit_out = nullptr;
    if ((long long)out_size == LOGN + 1) { loss_out = outf; logit_out = outf + 1; }
    else if ((long long)out_size == LOGN) { logit_out = outf; }
    else { loss_out = outf; }

    cudaFuncSetAttribute(dist_kernel, cudaFuncAttributeMaxDynamicSharedMemorySize, SM_TOTAL);

    prep_kernel<<<B2, 128>>>(f, s);
    gt_kernel<<<B2, 256>>>(f, s, label);

    dim3 grid(B2 / TN, B2 / TM);
    dist_kernel<<<grid, 256, SM_TOTAL>>>(logit_out ? logit_out : outf,
                                         logit_out != nullptr ? 1 : 0);

    if (loss_out) loss_kernel<<<1, 1024>>>(loss_out);
}